// round 12
// baseline (speedup 1.0000x reference)
#include <cuda_runtime.h>
#include <cstdint>

#define BATCH 16
#define CDIM 256
#define NPIX 10000
#define KDET 100
#define KREC 25
#define TPAD 20

// ---------------- scratch (static device globals) ----------------
__device__ float g_pq[6 * 2500];              // pos projections on 50x50 grid
__device__ float g_peT[2500 * CDIM];          // transposed pos_embed [pix][c]
__device__ unsigned g_keys[BATCH * NPIX];     // monotone-transformed margin keys
__device__ unsigned g_hist[BATCH * 256];      // per-batch top-byte histogram
__device__ int g_idx[BATCH * KDET];           // top-100 indices per batch

// ---------------- f32x2 packed helpers ----------------
__device__ __forceinline__ unsigned long long pk2(float a, float b) {
    unsigned long long r;
    asm("mov.b64 %0, {%1,%2};" : "=l"(r) : "f"(a), "f"(b));
    return r;
}
__device__ __forceinline__ void upk2(unsigned long long v, float& a, float& b) {
    asm("mov.b64 {%0,%1}, %2;" : "=f"(a), "=f"(b) : "l"(v));
}
__device__ __forceinline__ unsigned long long fma2(unsigned long long a, unsigned long long b, unsigned long long c) {
    unsigned long long d;
    asm("fma.rn.f32x2 %0, %1, %2, %3;" : "=l"(d) : "l"(a), "l"(b), "l"(c));
    return d;
}
__device__ __forceinline__ unsigned key_xform(float f) {
    unsigned u = __float_as_uint(f);
    return (u & 0x80000000u) ? ~u : (u | 0x80000000u);
}
__device__ __forceinline__ void bil_coord(int o, int& i0, int& i1, float& t) {
    float s = (o + 0.5f) * 0.5f - 0.5f; s = fminf(fmaxf(s, 0.f), 49.f);
    i0 = (int)floorf(s); i1 = min(i0 + 1, 49); t = s - (float)i0;
}

// ---------------- K1: fused pe transpose (632 blks) + pos projection (10 blks) + hist zero (1) ----
__global__ void __launch_bounds__(256) pos_prep_kernel(
        const float* __restrict__ pe,
        const float* __restrict__ Wc, const float* __restrict__ Wb) {
    int bid = blockIdx.x;
    int tid = threadIdx.x;
    if (bid < 632) {
        // transpose pe [256][2500] -> g_peT [2500][256], 32x32 tile
        __shared__ float t[32][33];
        int pix0 = (bid % 79) * 32, c0 = (bid / 79) * 32;
        int tx = tid % 32, ty = tid / 32;   // 32 x 8
        #pragma unroll
        for (int r = 0; r < 4; r++) {
            int c = c0 + ty + r * 8, pix = pix0 + tx;
            if (pix < 2500) t[ty + r * 8][tx] = pe[(size_t)c * 2500 + pix];
        }
        __syncthreads();
        #pragma unroll
        for (int r = 0; r < 4; r++) {
            int pix = pix0 + ty + r * 8, c = c0 + tx;
            if (pix < 2500) g_peT[(size_t)pix * CDIM + c] = t[tx][ty + r * 8];
        }
    } else if (bid < 642) {
        // project pe onto the 6 head rows at 50x50 resolution
        __shared__ float ws[6 * 256];
        for (int i = tid; i < 512; i += 256) ws[i] = Wc[i];
        for (int i = tid; i < 1024; i += 256) ws[512 + i] = Wb[i];
        __syncthreads();
        int pix = (bid - 632) * 256 + tid;
        if (pix >= 2500) return;
        float a0 = 0, a1 = 0, a2 = 0, a3 = 0, a4 = 0, a5 = 0;
        #pragma unroll 8
        for (int c = 0; c < 256; c++) {
            float p = __ldg(pe + (size_t)c * 2500 + pix);
            a0 += p * ws[c];        a1 += p * ws[256 + c];
            a2 += p * ws[512 + c];  a3 += p * ws[768 + c];
            a4 += p * ws[1024 + c]; a5 += p * ws[1280 + c];
        }
        g_pq[pix] = a0;            g_pq[2500 + pix] = a1;
        g_pq[5000 + pix] = a2;     g_pq[7500 + pix] = a3;
        g_pq[10000 + pix] = a4;    g_pq[12500 + pix] = a5;
    } else {
        // zero the per-batch histogram (needed every graph replay)
        for (int i = tid; i < BATCH * 256; i += 256) g_hist[i] = 0u;
    }
}

// ---------------- K2: stream x once; emit cls/bbox/keys + top-byte histogram ----------------
__global__ void __launch_bounds__(128) main_pass_kernel(
        const float* __restrict__ x,
        const float* __restrict__ bc, const float* __restrict__ bb,
        const float* __restrict__ Wc, const float* __restrict__ Wb,
        float* __restrict__ out_cls, float* __restrict__ out_bb) {
    __shared__ unsigned long long ws2[6 * 256];
    __shared__ unsigned hist2[512];            // block spans at most 2 batches
    int tid = threadIdx.x;
    for (int i = tid; i < 1536; i += 128) {
        float v = (i < 512) ? Wc[i] : Wb[i - 512];
        ws2[i] = pk2(v, v);
    }
    for (int i = tid; i < 512; i += 128) hist2[i] = 0u;
    __syncthreads();
    int id = blockIdx.x * 128 + tid;
    int b = id / (NPIX / 2);
    int b0 = (blockIdx.x * 128) / (NPIX / 2);
    int n2 = (id % (NPIX / 2)) * 2;
    const float* base = x + (size_t)b * CDIM * NPIX + n2;
    unsigned long long acc0 = 0, acc1 = 0, acc2 = 0, acc3 = 0, acc4 = 0, acc5 = 0;
    unsigned long long A[16], B[16];
    #pragma unroll
    for (int i = 0; i < 16; i++)
        A[i] = __ldg(reinterpret_cast<const unsigned long long*>(base + (size_t)i * NPIX));
    for (int c0 = 0; c0 < 256; c0 += 32) {
        #pragma unroll
        for (int i = 0; i < 16; i++)
            B[i] = __ldg(reinterpret_cast<const unsigned long long*>(base + (size_t)(c0 + 16 + i) * NPIX));
        #pragma unroll
        for (int i = 0; i < 16; i++) {
            int c = c0 + i;
            unsigned long long v = A[i];
            acc0 = fma2(v, ws2[c], acc0);
            acc1 = fma2(v, ws2[256 + c], acc1);
            acc2 = fma2(v, ws2[512 + c], acc2);
            acc3 = fma2(v, ws2[768 + c], acc3);
            acc4 = fma2(v, ws2[1024 + c], acc4);
            acc5 = fma2(v, ws2[1280 + c], acc5);
        }
        if (c0 + 32 < 256) {
            #pragma unroll
            for (int i = 0; i < 16; i++)
                A[i] = __ldg(reinterpret_cast<const unsigned long long*>(base + (size_t)(c0 + 32 + i) * NPIX));
        }
        #pragma unroll
        for (int i = 0; i < 16; i++) {
            int c = c0 + 16 + i;
            unsigned long long v = B[i];
            acc0 = fma2(v, ws2[c], acc0);
            acc1 = fma2(v, ws2[256 + c], acc1);
            acc2 = fma2(v, ws2[512 + c], acc2);
            acc3 = fma2(v, ws2[768 + c], acc3);
            acc4 = fma2(v, ws2[1024 + c], acc4);
            acc5 = fma2(v, ws2[1280 + c], acc5);
        }
    }
    float a0x, a0y, a1x, a1y, a2x, a2y, a3x, a3y, a4x, a4y, a5x, a5y;
    upk2(acc0, a0x, a0y); upk2(acc1, a1x, a1y); upk2(acc2, a2x, a2y);
    upk2(acc3, a3x, a3y); upk2(acc4, a4x, a4y); upk2(acc5, a5x, a5y);

    int yy = n2 / 100, xxa = n2 % 100;
    int y0, y1, x0a, x1a, x0b, x1b; float ty, txa, txb;
    bil_coord(yy, y0, y1, ty);
    bil_coord(xxa, x0a, x1a, txa);
    bil_coord(xxa + 1, x0b, x1b, txb);
    float pA[6], pB[6];
    #pragma unroll
    for (int w = 0; w < 6; w++) {
        const float* p = g_pq + (size_t)w * 2500;
        float r0a = p[y0 * 50 + x0a] * (1.f - txa) + p[y0 * 50 + x1a] * txa;
        float r1a = p[y1 * 50 + x0a] * (1.f - txa) + p[y1 * 50 + x1a] * txa;
        pA[w] = r0a * (1.f - ty) + r1a * ty;
        float r0b = p[y0 * 50 + x0b] * (1.f - txb) + p[y0 * 50 + x1b] * txb;
        float r1b = p[y1 * 50 + x0b] * (1.f - txb) + p[y1 * 50 + x1b] * txb;
        pB[w] = r0b * (1.f - ty) + r1b * ty;
    }
    float bc0 = bc[0], bc1 = bc[1];
    float bb0 = bb[0], bb1 = bb[1], bb2 = bb[2], bb3 = bb[3];
    float l0x = a0x + pA[0] + bc0, l0y = a0y + pB[0] + bc0;
    float l1x = a1x + pA[1] + bc1, l1y = a1y + pB[1] + bc1;
    size_t co = ((size_t)b * NPIX + n2) * 2;
    *reinterpret_cast<float4*>(out_cls + co) = make_float4(l0x, l1x, l0y, l1y);
    size_t bo = ((size_t)b * NPIX + n2) * 4;
    *reinterpret_cast<float4*>(out_bb + bo) =
        make_float4(a2x + pA[2] + bb0, a3x + pA[3] + bb1, a4x + pA[4] + bb2, a5x + pA[5] + bb3);
    *reinterpret_cast<float4*>(out_bb + bo + 4) =
        make_float4(a2y + pB[2] + bb0, a3y + pB[3] + bb1, a4y + pB[4] + bb2, a5y + pB[5] + bb3);
    unsigned k0 = key_xform(l1x - l0x), k1 = key_xform(l1y - l0y);
    *reinterpret_cast<uint2*>(g_keys + (size_t)b * NPIX + n2) = make_uint2(k0, k1);
    int loc = (b - b0) * 256;
    atomicAdd(&hist2[loc + (k0 >> 24)], 1u);
    atomicAdd(&hist2[loc + (k1 >> 24)], 1u);
    __syncthreads();
    for (int i = tid; i < 512; i += 128) {
        unsigned v = hist2[i];
        if (v) atomicAdd(&g_hist[(b0 + (i >> 8)) * 256 + (i & 255)], v);
    }
}

// ---------------- K3: top-100 select: precomputed hist -> one compact scan -> radix on candidates
#define TKT 1024
#define COMP_CAP 2048
__global__ void __launch_bounds__(TKT) topk_kernel() {
    __shared__ unsigned long long comp[COMP_CAP];
    __shared__ unsigned long long cand[256];
    __shared__ unsigned hist[2048];
    __shared__ unsigned tot[256];
    __shared__ unsigned s_prefix;
    __shared__ int s_kk, s_cnt, s_m;
    int b = blockIdx.x, tid = threadIdx.x;
    const unsigned* gk = g_keys + (size_t)b * NPIX;
    unsigned* myh = hist + ((tid >> 5) & 7) * 256;

    if (tid == 0) { s_prefix = 0u; s_kk = KDET; s_cnt = 0; s_m = 0; }
    if (tid < 256) tot[tid] = g_hist[b * 256 + tid];
    __syncthreads();

    // warp 0: suffix scan of the precomputed top-byte histogram
    if (tid < 32) {
        unsigned v[8], gs = 0;
        #pragma unroll
        for (int i = 0; i < 8; i++) { v[i] = tot[tid * 8 + i]; gs += v[i]; }
        unsigned s = gs;
        #pragma unroll
        for (int off = 1; off < 32; off <<= 1) {
            unsigned t = __shfl_down_sync(0xFFFFFFFFu, s, off);
            if (tid + off < 32) s += t;
        }
        unsigned run = s - gs, cum = 0;
        #pragma unroll
        for (int i = 7; i >= 0; i--) { cum += v[i]; tot[tid * 8 + i] = cum + run; }
    }
    __syncthreads();
    if (tid < 256) {
        unsigned Sb = tot[tid];
        unsigned Sb1 = (tid < 255) ? tot[tid + 1] : 0u;
        if (Sb >= (unsigned)KDET && Sb1 < (unsigned)KDET) {
            s_prefix = (unsigned)tid << 24;
            s_kk = KDET - (int)Sb1;
        }
    }
    __syncthreads();
    unsigned sel1 = s_prefix >> 24;

    // single compact scan: keys with top byte >= sel1
    for (int i = tid; i < NPIX; i += TKT) {
        unsigned u = gk[i];
        if ((u >> 24) >= sel1) {
            int p = atomicAdd(&s_m, 1);
            if (p < COMP_CAP)
                comp[p] = ((unsigned long long)u << 32) | (unsigned)(~(unsigned)i);
        }
    }
    __syncthreads();
    bool ok = (s_m <= COMP_CAP);
    int M = ok ? s_m : NPIX;

    // radix passes 1-3 over compacted list (fallback: full scan)
    for (int pass = 1; pass < 4; pass++) {
        int shift = 24 - 8 * pass;
        unsigned himask = 0xFFFFFFFFu << (shift + 8);
        for (int i = tid; i < 2048; i += TKT) hist[i] = 0;
        __syncthreads();
        unsigned prefix = s_prefix;
        int kk = s_kk;
        for (int i = tid; i < M; i += TKT) {
            unsigned u = ok ? (unsigned)(comp[i] >> 32) : gk[i];
            if (((u ^ prefix) & himask) == 0) atomicAdd(&myh[(u >> shift) & 255], 1u);
        }
        __syncthreads();
        if (tid < 256) {
            unsigned s = 0;
            #pragma unroll
            for (int cp = 0; cp < 8; cp++) s += hist[cp * 256 + tid];
            tot[tid] = s;
        }
        __syncthreads();
        if (tid < 32) {
            unsigned v[8], gs = 0;
            #pragma unroll
            for (int i = 0; i < 8; i++) { v[i] = tot[tid * 8 + i]; gs += v[i]; }
            unsigned s = gs;
            #pragma unroll
            for (int off = 1; off < 32; off <<= 1) {
                unsigned t = __shfl_down_sync(0xFFFFFFFFu, s, off);
                if (tid + off < 32) s += t;
            }
            unsigned run = s - gs, cum = 0;
            #pragma unroll
            for (int i = 7; i >= 0; i--) { cum += v[i]; tot[tid * 8 + i] = cum + run; }
        }
        __syncthreads();
        if (tid < 256) {
            unsigned Sb = tot[tid];
            unsigned Sb1 = (tid < 255) ? tot[tid + 1] : 0u;
            if (Sb >= (unsigned)kk && Sb1 < (unsigned)kk) {
                s_prefix = prefix | ((unsigned)tid << shift);
                s_kk = kk - (int)Sb1;
            }
        }
        __syncthreads();
    }
    unsigned T = s_prefix;

    // collect candidates >= T
    for (int i = tid; i < M; i += TKT) {
        unsigned long long e; unsigned u;
        if (ok) { e = comp[i]; u = (unsigned)(e >> 32); }
        else { u = gk[i]; e = ((unsigned long long)u << 32) | (unsigned)(~(unsigned)i); }
        if (u >= T) {
            int p = atomicAdd(&s_cnt, 1);
            if (p < 256) cand[p] = e;
        }
    }
    __syncthreads();
    int cnt = min(s_cnt, 256);
    for (int i = cnt + tid; i < 256; i += TKT) cand[i] = 0ull;
    __syncthreads();

    // bitonic sort 256 descending => value desc, index asc on ties
    for (int ksz = 2; ksz <= 256; ksz <<= 1) {
        for (int j = ksz >> 1; j > 0; j >>= 1) {
            if (tid < 256) {
                int l = tid ^ j;
                if (l > tid) {
                    unsigned long long a = cand[tid], c2 = cand[l];
                    bool dirDesc = ((tid & ksz) == 0);
                    if ((a < c2) == dirDesc) { cand[tid] = c2; cand[l] = a; }
                }
            }
            __syncthreads();
        }
    }
    if (tid < KDET)
        g_idx[b * KDET + tid] = (int)(~((unsigned)(cand[tid] & 0xFFFFFFFFull)));
}

// ---------------- K4: fused gather + det/rec MLPs; f32x2; TP=16 (125 blocks, 1 wave) ----------------
#define MLP_SMEM ((2 * 256 * TPAD + 32 * 257) * 4)
#define TP 16
#define DET_BLOCKS 100

__device__ __forceinline__ void run_layer16(const float* __restrict__ Wg, float bj,
                                            const float* __restrict__ bufIn,
                                            float* __restrict__ Wt,
                                            unsigned long long acc[8]) {
    int tid = threadIdx.x;
    unsigned long long binit = pk2(bj, bj);
    #pragma unroll
    for (int p = 0; p < 8; p++) acc[p] = binit;
    for (int kc = 0; kc < 256; kc += 32) {
        #pragma unroll
        for (int r = 0; r < 8; r++) {
            int e = (r * 256 + tid) * 4;
            int j2 = e >> 5, i = e & 31;
            float4 w4 = *reinterpret_cast<const float4*>(Wg + j2 * 256 + kc + i);
            Wt[(i + 0) * 257 + j2] = w4.x;
            Wt[(i + 1) * 257 + j2] = w4.y;
            Wt[(i + 2) * 257 + j2] = w4.z;
            Wt[(i + 3) * 257 + j2] = w4.w;
        }
        __syncthreads();
        #pragma unroll 8
        for (int k = 0; k < 32; k++) {
            float w = Wt[k * 257 + tid];
            unsigned long long wd = pk2(w, w);
            const ulonglong2* tv = reinterpret_cast<const ulonglong2*>(bufIn + (kc + k) * TPAD);
            #pragma unroll
            for (int q = 0; q < 4; q++) {
                ulonglong2 p2 = tv[q];
                acc[2 * q]     = fma2(p2.x, wd, acc[2 * q]);
                acc[2 * q + 1] = fma2(p2.y, wd, acc[2 * q + 1]);
            }
        }
        __syncthreads();
    }
}

__global__ void __launch_bounds__(256) mlp_kernel(
    const float* __restrict__ x,
    const float* __restrict__ dW1, const float* __restrict__ db1,
    const float* __restrict__ dW2, const float* __restrict__ db2,
    const float* __restrict__ dW3, const float* __restrict__ db3,
    const float* __restrict__ rW1, const float* __restrict__ rb1,
    const float* __restrict__ rW2, const float* __restrict__ rb2,
    const float* __restrict__ rW3, const float* __restrict__ rb3,
    const float* __restrict__ det_q, const float* __restrict__ rec_q,
    float* __restrict__ out_det, float* __restrict__ out_rec) {
    extern __shared__ float sh[];
    float* bufA = sh;
    float* bufB = sh + 256 * TPAD;
    float* Wt   = sh + 2 * 256 * TPAD;
    int tid = threadIdx.x;
    bool isDet = blockIdx.x < DET_BLOCKS;
    int blk = isDet ? blockIdx.x : (blockIdx.x - DET_BLOCKS);
    int kq = isDet ? KDET : KREC;

    // fused gather: x[b,:,idx] + bilinear(peT) for this block's 16 tokens
    #pragma unroll
    for (int t = 0; t < TP; t++) {
        int g = blk * TP + t;
        int bq = isDet ? g : ((g / KREC) * KDET + (g % KREC));
        int idx = g_idx[bq];
        int bb_ = bq / KDET;
        int yy = idx / 100, xx = idx % 100;
        int y0, y1, x0, x1; float ty, tx;
        bil_coord(yy, y0, y1, ty);
        bil_coord(xx, x0, x1, tx);
        float v00 = g_peT[(size_t)(y0 * 50 + x0) * CDIM + tid];
        float v01 = g_peT[(size_t)(y0 * 50 + x1) * CDIM + tid];
        float v10 = g_peT[(size_t)(y1 * 50 + x0) * CDIM + tid];
        float v11 = g_peT[(size_t)(y1 * 50 + x1) * CDIM + tid];
        float r0 = v00 * (1.f - ty) + v10 * ty;
        float r1 = v01 * (1.f - ty) + v11 * ty;
        float pos = r0 * (1.f - tx) + r1 * tx;
        float xv = __ldg(x + ((size_t)(bb_ * CDIM + tid)) * NPIX + idx);
        bufA[tid * TPAD + t] = xv + pos;
    }
    __syncthreads();

    const float* W1 = isDet ? dW1 : rW1; const float* B1 = isDet ? db1 : rb1;
    const float* W2 = isDet ? dW2 : rW2; const float* B2 = isDet ? db2 : rb2;
    const float* W3 = isDet ? dW3 : rW3; const float* B3 = isDet ? db3 : rb3;
    const float* qv = isDet ? det_q : rec_q;
    float* outp = isDet ? out_det : out_rec;

    unsigned long long acc[8];
    run_layer16(W1, B1[tid], bufA, Wt, acc);
    #pragma unroll
    for (int p = 0; p < 8; p++) {
        float u, v; upk2(acc[p], u, v);
        *reinterpret_cast<unsigned long long*>(&bufB[tid * TPAD + 2 * p]) =
            pk2(fmaxf(u, 0.f), fmaxf(v, 0.f));
    }
    __syncthreads();

    run_layer16(W2, B2[tid], bufB, Wt, acc);
    #pragma unroll
    for (int p = 0; p < 8; p++) {
        float u, v; upk2(acc[p], u, v);
        *reinterpret_cast<unsigned long long*>(&bufA[tid * TPAD + 2 * p]) =
            pk2(fmaxf(u, 0.f), fmaxf(v, 0.f));
    }
    __syncthreads();

    run_layer16(W3, B3[tid], bufA, Wt, acc);
    #pragma unroll
    for (int p = 0; p < 8; p++) {
        float u, v; upk2(acc[p], u, v);
        int g0 = blk * TP + 2 * p;
        int qi0 = g0 % kq, qi1 = (g0 + 1) % kq;
        outp[(size_t)g0 * 256 + tid]       = u + qv[qi0 * 256 + tid];
        outp[(size_t)(g0 + 1) * 256 + tid] = v + qv[qi1 * 256 + tid];
    }
}

// ---------------- launch ----------------
extern "C" void kernel_launch(void* const* d_in, const int* in_sizes, int n_in,
                              void* d_out, int out_size) {
    const float* x     = (const float*)d_in[0];
    const float* Wc    = (const float*)d_in[1];
    const float* bc    = (const float*)d_in[2];
    const float* Wb    = (const float*)d_in[3];
    const float* bb    = (const float*)d_in[4];
    const float* dW1   = (const float*)d_in[5];
    const float* db1   = (const float*)d_in[6];
    const float* dW2   = (const float*)d_in[7];
    const float* db2   = (const float*)d_in[8];
    const float* dW3   = (const float*)d_in[9];
    const float* db3   = (const float*)d_in[10];
    const float* rW1   = (const float*)d_in[11];
    const float* rb1   = (const float*)d_in[12];
    const float* rW2   = (const float*)d_in[13];
    const float* rb2   = (const float*)d_in[14];
    const float* rW3   = (const float*)d_in[15];
    const float* rb3   = (const float*)d_in[16];
    const float* det_q = (const float*)d_in[17];
    const float* rec_q = (const float*)d_in[18];
    const float* pe    = (const float*)d_in[19];

    float* out = (float*)d_out;
    float* out_det = out;               // 16*100*256 = 409600
    float* out_rec = out + 409600;      // 16*25*256  = 102400
    float* out_cls = out + 512000;      // 16*10000*2 = 320000
    float* out_bb  = out + 832000;      // 16*10000*4 = 640000

    pos_prep_kernel<<<643, 256>>>(pe, Wc, Wb);
    main_pass_kernel<<<625, 128>>>(x, bc, bb, Wc, Wb, out_cls, out_bb);
    topk_kernel<<<BATCH, TKT>>>();

    cudaFuncSetAttribute(mlp_kernel, cudaFuncAttributeMaxDynamicSharedMemorySize, MLP_SMEM);
    mlp_kernel<<<125, 256, MLP_SMEM>>>(x, dW1, db1, dW2, db2, dW3, db3,
                                       rW1, rb1, rW2, rb2, rW3, rb3,
                                       det_q, rec_q, out_det, out_rec);
}